// round 1
// baseline (speedup 1.0000x reference)
#include <cuda_runtime.h>
#include <math.h>

// Problem constants
#define NB 32     // batch
#define SS 12     // seq len
#define FF 128    // features
#define KH 8      // heads
#define HH 64     // head dim
#define CC 64     // out channels
#define NN 512    // nodes
#define SEGS 4    // n-segments for Wf reduction

// Scratch (no allocations allowed)
__device__ float g_v[NB * CC];                 // per-batch feature vector v[b][c]
__device__ float g_wfpart[SEGS * CC * CC];     // partial Wf reductions [seg][c2][c]

// ---------------------------------------------------------------------------
// K1: v[b][c] = sum_j elu( x_last[b] . W_heads[:, :, j] ) * W_out[j][c]
// One block per batch, 512 threads.
// ---------------------------------------------------------------------------
__global__ void __launch_bounds__(512) k1_features(
    const float* __restrict__ x,
    const float* __restrict__ W_heads,
    const float* __restrict__ W_out)
{
    int b = blockIdx.x;
    int tid = threadIdx.x;

    __shared__ float xl[FF];
    __shared__ float hp[KH * HH];
    __shared__ float red[512];

    if (tid < FF) xl[tid] = x[b * SS * FF + (SS - 1) * FF + tid];
    __syncthreads();

    // Wh[k][h]: tid -> (k = tid/64, h = tid%64)
    {
        int k = tid >> 6;
        int h = tid & 63;
        const float* w = W_heads + (k * FF) * HH + h;   // stride HH over f
        float acc = 0.f;
        #pragma unroll 8
        for (int f = 0; f < FF; ++f)
            acc = fmaf(xl[f], w[f * HH], acc);
        // elu (alpha=1)
        hp[tid] = (acc > 0.f) ? acc : expm1f(acc);
    }
    __syncthreads();

    // v[c] = sum_{j=0..511} hp[j] * W_out[j][c]; split j into 8 parts
    {
        int c = tid & 63;
        int part = tid >> 6;
        float acc = 0.f;
        int j0 = part * 64;
        #pragma unroll 8
        for (int j = j0; j < j0 + 64; ++j)
            acc = fmaf(hp[j], W_out[j * CC + c], acc);
        red[part * 64 + c] = acc;
    }
    __syncthreads();
    for (int s = 4; s >= 1; s >>= 1) {
        int c = tid & 63;
        int part = tid >> 6;
        if (part < s) red[part * 64 + c] += red[(part + s) * 64 + c];
        __syncthreads();
    }
    if (tid < CC) g_v[b * CC + tid] = red[tid];
}

// ---------------------------------------------------------------------------
// K2: g_wfpart[seg][c2][c] = sum_{n in seg} Wf[c2][n*64 + c]
// Grid = 64*SEGS blocks, 256 threads. float4 coalesced streaming of 8.4 MB.
// ---------------------------------------------------------------------------
__global__ void __launch_bounds__(256) k2_wfsum(const float* __restrict__ Wf)
{
    int c2  = blockIdx.x >> 2;        // 0..63
    int seg = blockIdx.x & 3;         // 0..3
    int tid = threadIdx.x;            // 256
    int lane = tid & 15;              // which float4 within a 64-float row
    int np   = tid >> 4;              // 16 n-partitions

    const float4* base = (const float4*)(Wf + (size_t)c2 * (NN * CC));

    float4 acc = make_float4(0.f, 0.f, 0.f, 0.f);
    #pragma unroll
    for (int i = 0; i < 8; ++i) {
        int n = seg * 128 + np * 8 + i;          // 128 rows per segment
        float4 v = base[n * 16 + lane];          // row = 16 float4
        acc.x += v.x; acc.y += v.y; acc.z += v.z; acc.w += v.w;
    }

    __shared__ float4 sred[256];
    sred[tid] = acc;
    __syncthreads();
    for (int s = 8; s >= 1; s >>= 1) {
        if (np < s) {
            float4 o = sred[(np + s) * 16 + lane];
            float4 m = sred[np * 16 + lane];
            m.x += o.x; m.y += o.y; m.z += o.z; m.w += o.w;
            sred[np * 16 + lane] = m;
        }
        __syncthreads();
    }
    if (tid < 16) {
        ((float4*)(g_wfpart + (size_t)seg * CC * CC + c2 * CC))[lane] = sred[lane];
    }
}

// ---------------------------------------------------------------------------
// K3: out[b][c2] = bf[c2] + sum_c v[b][c] * (sum_seg g_wfpart[seg][c2][c])
// Grid = 32 blocks, 64 threads.
// ---------------------------------------------------------------------------
__global__ void __launch_bounds__(64) k3_final(
    const float* __restrict__ bf,
    float* __restrict__ out)
{
    int b = blockIdx.x;
    int c2 = threadIdx.x;

    __shared__ float v[CC];
    v[c2] = g_v[b * CC + c2];
    __syncthreads();

    float acc = bf[c2];
    const float* w0 = g_wfpart + c2 * CC;
    #pragma unroll 8
    for (int c = 0; c < CC; ++c) {
        float w = w0[c]
                + w0[1 * CC * CC + c]
                + w0[2 * CC * CC + c]
                + w0[3 * CC * CC + c];
        acc = fmaf(v[c], w, acc);
    }
    out[b * CC + c2] = acc;
}

// ---------------------------------------------------------------------------
// Inputs (metadata order):
//   0: x        (32,12,128)   f32
//   1: W_heads  (8,128,64)    f32
//   2: a1_heads (8,64)        f32   (unused: softmax over identical rows is uniform)
//   3: a2_heads (8,64)        f32   (unused)
//   4: W_out    (512,64)      f32
//   5: a1_out   (64)          f32   (unused)
//   6: a2_out   (64)          f32   (unused)
//   7: Wf       (64,32768)    f32
//   8: bf       (64)          f32
// Output: (32,64) f32
// ---------------------------------------------------------------------------
extern "C" void kernel_launch(void* const* d_in, const int* in_sizes, int n_in,
                              void* d_out, int out_size)
{
    const float* x       = (const float*)d_in[0];
    const float* W_heads = (const float*)d_in[1];
    const float* W_out   = (const float*)d_in[4];
    const float* Wf      = (const float*)d_in[7];
    const float* bf      = (const float*)d_in[8];
    float* out = (float*)d_out;

    // K2 (8.4 MB stream) and K1 are independent; K3 consumes both.
    k2_wfsum<<<CC * SEGS, 256>>>(Wf);
    k1_features<<<NB, 512>>>(x, W_heads, W_out);
    k3_final<<<NB, CC>>>(bf, out);
}

// round 2
// speedup vs baseline: 1.3222x; 1.3222x over previous
#include <cuda_runtime.h>
#include <math.h>

// Problem constants
#define NB 32     // batch
#define SS 12     // seq len
#define FF 128    // features
#define KH 8      // heads
#define HH 64     // head dim
#define CC 64     // out channels
#define NN 512    // nodes
#define SEGS 16   // n-segments for Wf reduction (512/16 = 32 rows/segment)

#define WF_BLOCKS (CC * SEGS)   // 1024 wfsum blocks
#define TOTAL_BLOCKS (WF_BLOCKS + NB)

// Scratch (no allocations allowed)
__device__ float g_v[NB * CC];                 // per-batch feature vector v[b][c]
__device__ float g_wfpart[SEGS * CC * CC];     // partial Wf reductions [seg][c2][c]

// ---------------------------------------------------------------------------
// Kernel A (fused, block-specialized):
//   blocks [0, 1024):  g_wfpart[seg][c2][c] = sum_{n in seg} Wf[c2][n*64+c]
//                      (8.4 MB coalesced float4 stream, 2 loads/thread)
//   blocks [1024, 1056): per-batch features
//                      v[b][c] = sum_j elu(x_last[b] . W_heads[:,:,j]) * W_out[j][c]
// 256 threads/block.
// ---------------------------------------------------------------------------
__global__ void __launch_bounds__(256) kA_fused(
    const float* __restrict__ Wf,
    const float* __restrict__ x,
    const float* __restrict__ W_heads,
    const float* __restrict__ W_out)
{
    int bid = blockIdx.x;
    int tid = threadIdx.x;

    if (bid < WF_BLOCKS) {
        // ---- Wf segment reduction ----
        int c2  = bid >> 4;          // 0..63
        int seg = bid & 15;          // 0..15
        int lane = tid & 15;         // float4 index within 64-float row
        int np   = tid >> 4;         // 16 n-partitions, 2 rows each

        const float4* base = (const float4*)(Wf + (size_t)c2 * (NN * CC));

        float4 acc;
        {
            int n0 = seg * 32 + np * 2;
            float4 v0 = base[(n0 + 0) * 16 + lane];
            float4 v1 = base[(n0 + 1) * 16 + lane];
            acc.x = v0.x + v1.x; acc.y = v0.y + v1.y;
            acc.z = v0.z + v1.z; acc.w = v0.w + v1.w;
        }

        __shared__ float4 sred[256];
        sred[tid] = acc;
        __syncthreads();
        #pragma unroll
        for (int s = 8; s >= 1; s >>= 1) {
            if (np < s) {
                float4 o = sred[(np + s) * 16 + lane];
                float4 m = sred[np * 16 + lane];
                m.x += o.x; m.y += o.y; m.z += o.z; m.w += o.w;
                sred[np * 16 + lane] = m;
            }
            __syncthreads();
        }
        if (tid < 16) {
            ((float4*)(g_wfpart + (size_t)seg * CC * CC + c2 * CC))[lane] = sred[lane];
        }
    } else {
        // ---- per-batch feature vector ----
        int b = bid - WF_BLOCKS;

        __shared__ float xl[FF];
        __shared__ float hp[KH * HH];
        __shared__ float red[256];

        if (tid < FF) xl[tid] = x[b * SS * FF + (SS - 1) * FF + tid];
        __syncthreads();

        // Wh[k][h], elu: 512 outputs, 2 per thread
        #pragma unroll
        for (int rep = 0; rep < 2; ++rep) {
            int j = tid + rep * 256;
            int k = j >> 6;
            int h = j & 63;
            const float* w = W_heads + (k * FF) * HH + h;   // lanes contiguous in h
            float acc = 0.f;
            #pragma unroll 8
            for (int f = 0; f < FF; ++f)
                acc = fmaf(xl[f], w[f * HH], acc);
            hp[j] = (acc > 0.f) ? acc : expm1f(acc);   // elu (alpha=1)
        }
        __syncthreads();

        // v[c] = sum_{j=0..511} hp[j] * W_out[j][c]; 4 j-parts of 128
        {
            int c = tid & 63;
            int part = tid >> 6;
            float acc = 0.f;
            int j0 = part * 128;
            #pragma unroll 8
            for (int j = j0; j < j0 + 128; ++j)
                acc = fmaf(hp[j], W_out[j * CC + c], acc);
            red[part * 64 + c] = acc;
        }
        __syncthreads();
        #pragma unroll
        for (int s = 2; s >= 1; s >>= 1) {
            int c = tid & 63;
            int part = tid >> 6;
            if (part < s) red[part * 64 + c] += red[(part + s) * 64 + c];
            __syncthreads();
        }
        if (tid < CC) g_v[b * CC + tid] = red[tid];
    }
}

// ---------------------------------------------------------------------------
// Kernel B: final output.
// Grid = 64 blocks (one per c2), 64 threads (one per c).
//   sw[c]  = sum_seg g_wfpart[seg][c2][c]     (coalesced: lanes contiguous in c)
//   out[b][c2] = bf[c2] + sum_c v[b][c] * sw[c]  (threads b<32 do shared dots)
// ---------------------------------------------------------------------------
__global__ void __launch_bounds__(64) kB_final(
    const float* __restrict__ bf,
    float* __restrict__ out)
{
    int c2 = blockIdx.x;
    int tid = threadIdx.x;    // = c for phase 1, = b for phase 2

    __shared__ float sv[NB * CC];
    __shared__ float sw[CC];

    // load all v (coalesced): 64 threads x 32 rows
    #pragma unroll
    for (int b = 0; b < NB; ++b)
        sv[b * CC + tid] = g_v[b * CC + tid];

    // Wfsum row for this c2 (coalesced over c)
    {
        float w = 0.f;
        const float* p = g_wfpart + c2 * CC + tid;
        #pragma unroll
        for (int seg = 0; seg < SEGS; ++seg)
            w += p[seg * CC * CC];
        sw[tid] = w;
    }
    __syncthreads();

    if (tid < NB) {
        int b = tid;
        float acc = bf[c2];
        #pragma unroll 8
        for (int c = 0; c < CC; ++c)
            acc = fmaf(sv[b * CC + c], sw[c], acc);
        out[b * CC + c2] = acc;
    }
}

// ---------------------------------------------------------------------------
// Inputs (metadata order):
//   0: x        (32,12,128)   f32
//   1: W_heads  (8,128,64)    f32
//   2: a1_heads (8,64)        f32   (unused: softmax over identical rows is uniform)
//   3: a2_heads (8,64)        f32   (unused)
//   4: W_out    (512,64)      f32
//   5: a1_out   (64)          f32   (unused)
//   6: a2_out   (64)          f32   (unused)
//   7: Wf       (64,32768)    f32
//   8: bf       (64)          f32
// Output: (32,64) f32
// ---------------------------------------------------------------------------
extern "C" void kernel_launch(void* const* d_in, const int* in_sizes, int n_in,
                              void* d_out, int out_size)
{
    const float* x       = (const float*)d_in[0];
    const float* W_heads = (const float*)d_in[1];
    const float* W_out   = (const float*)d_in[4];
    const float* Wf      = (const float*)d_in[7];
    const float* bf      = (const float*)d_in[8];
    float* out = (float*)d_out;

    kA_fused<<<TOTAL_BLOCKS, 256>>>(Wf, x, W_heads, W_out);
    kB_final<<<CC, 64>>>(bf, out);
}

// round 3
// speedup vs baseline: 1.3244x; 1.0017x over previous
#include <cuda_runtime.h>
#include <math.h>

// Problem constants
#define NB 32     // batch
#define SS 12     // seq len
#define FF 128    // features
#define KH 8      // heads
#define HH 64     // head dim
#define CC 64     // out channels
#define NN 512    // nodes
#define SEGS 16   // n-segments for Wf reduction (512/16 = 32 rows/segment)

#define WF_BLOCKS (CC * SEGS)   // 1024 wfsum blocks
#define TOTAL_BLOCKS (WF_BLOCKS + NB)

// Scratch (no allocations allowed)
__device__ float g_v[NB * CC];                 // per-batch feature vector v[b][c]
// Transposed partial layout: [c2][seg][c] -> kB reads one contiguous 4KB run per block
__device__ float g_wfpart[CC * SEGS * CC];

// ---------------------------------------------------------------------------
// Kernel A (fused, block-specialized):
//   blocks [0, 1024):  g_wfpart[c2][seg][c] = sum_{n in seg} Wf[c2][n*64+c]
//                      (8.4 MB coalesced float4 stream, 2 float4 loads/thread)
//   blocks [1024, 1056): per-batch features
//                      v[b][c] = sum_j elu(x_last[b] . W_heads[:,:,j]) * W_out[j][c]
// 256 threads/block.
// ---------------------------------------------------------------------------
__global__ void __launch_bounds__(256) kA_fused(
    const float* __restrict__ Wf,
    const float* __restrict__ x,
    const float* __restrict__ W_heads,
    const float* __restrict__ W_out)
{
    int bid = blockIdx.x;
    int tid = threadIdx.x;

    if (bid < WF_BLOCKS) {
        // ---- Wf segment reduction ----
        int c2  = bid >> 4;          // 0..63
        int seg = bid & 15;          // 0..15
        int lane = tid & 15;         // float4 index within 64-float row
        int np   = tid >> 4;         // 16 n-partitions, 2 rows each

        const float4* base = (const float4*)(Wf + (size_t)c2 * (NN * CC));

        float4 acc;
        {
            int n0 = seg * 32 + np * 2;
            float4 v0 = base[(n0 + 0) * 16 + lane];
            float4 v1 = base[(n0 + 1) * 16 + lane];
            acc.x = v0.x + v1.x; acc.y = v0.y + v1.y;
            acc.z = v0.z + v1.z; acc.w = v0.w + v1.w;
        }

        __shared__ float4 sred[256];
        sred[tid] = acc;
        __syncthreads();
        #pragma unroll
        for (int s = 8; s >= 1; s >>= 1) {
            if (np < s) {
                float4 o = sred[(np + s) * 16 + lane];
                float4 m = sred[np * 16 + lane];
                m.x += o.x; m.y += o.y; m.z += o.z; m.w += o.w;
                sred[np * 16 + lane] = m;
            }
            __syncthreads();
        }
        if (tid < 16) {
            ((float4*)(g_wfpart + ((size_t)c2 * SEGS + seg) * CC))[lane] = sred[lane];
        }
    } else {
        // ---- per-batch feature vector ----
        int b = bid - WF_BLOCKS;

        __shared__ float xl[FF];
        __shared__ float hp[KH * HH];
        __shared__ float red[256];

        if (tid < FF) xl[tid] = x[b * SS * FF + (SS - 1) * FF + tid];
        __syncthreads();

        // Wh[k][h], elu: 512 outputs, 2 per thread
        #pragma unroll
        for (int rep = 0; rep < 2; ++rep) {
            int j = tid + rep * 256;
            int k = j >> 6;
            int h = j & 63;
            const float* w = W_heads + (k * FF) * HH + h;   // lanes contiguous in h
            float acc = 0.f;
            #pragma unroll 8
            for (int f = 0; f < FF; ++f)
                acc = fmaf(xl[f], w[f * HH], acc);
            hp[j] = (acc > 0.f) ? acc : expm1f(acc);   // elu (alpha=1)
        }
        __syncthreads();

        // v[c] = sum_{j=0..511} hp[j] * W_out[j][c]; 4 j-parts of 128
        {
            int c = tid & 63;
            int part = tid >> 6;
            float acc = 0.f;
            int j0 = part * 128;
            #pragma unroll 8
            for (int j = j0; j < j0 + 128; ++j)
                acc = fmaf(hp[j], W_out[j * CC + c], acc);
            red[part * 64 + c] = acc;
        }
        __syncthreads();
        #pragma unroll
        for (int s = 2; s >= 1; s >>= 1) {
            int c = tid & 63;
            int part = tid >> 6;
            if (part < s) red[part * 64 + c] += red[(part + s) * 64 + c];
            __syncthreads();
        }
        if (tid < CC) g_v[b * CC + tid] = red[tid];
    }
}

// ---------------------------------------------------------------------------
// Kernel B: final output. Grid = 64 blocks (c2), 128 threads.
// All global loads issued up-front as independent float4s (one latency round):
//   - this c2's partials: 4KB contiguous (256 float4, 2/thread)
//   - g_v: 8KB (512 float4, 4/thread)
// Then: sw[c] = sum_seg part[seg][c]; out[b][c2] = bf[c2] + dot(v[b], sw).
// ---------------------------------------------------------------------------
__global__ void __launch_bounds__(128) kB_final(
    const float* __restrict__ bf,
    float* __restrict__ out)
{
    int c2 = blockIdx.x;
    int tid = threadIdx.x;

    __shared__ float4 tmp[SEGS * 16];    // [seg][lane4] partials for this c2
    __shared__ float  sv[NB * CC];       // all v
    __shared__ float  sw[CC];

    // Issue all global loads (independent, pipelined)
    const float4* pp = (const float4*)(g_wfpart + (size_t)c2 * SEGS * CC);
    float4 p0 = pp[tid];
    float4 p1 = pp[tid + 128];

    const float4* vp = (const float4*)g_v;
    float4 v0 = vp[tid];
    float4 v1 = vp[tid + 128];
    float4 v2 = vp[tid + 256];
    float4 v3 = vp[tid + 384];

    float bias = bf[c2];   // broadcast, L2/const

    tmp[tid] = p0;
    tmp[tid + 128] = p1;
    ((float4*)sv)[tid]       = v0;
    ((float4*)sv)[tid + 128] = v1;
    ((float4*)sv)[tid + 256] = v2;
    ((float4*)sv)[tid + 384] = v3;
    __syncthreads();

    // sw[c] = sum over 16 segs (64 threads, one per c)
    if (tid < CC) {
        const float* t = (const float*)tmp;
        float w = 0.f;
        #pragma unroll
        for (int s = 0; s < SEGS; ++s)
            w += t[s * CC + tid];
        sw[tid] = w;
    }
    __syncthreads();

    // out[b][c2]: tid -> b = tid/4, part = tid%4 (16 c's each), shuffle-reduce
    {
        int b = tid >> 2;
        int part = tid & 3;
        const float* svb = sv + b * CC + part * 16;
        const float* swp = sw + part * 16;
        float acc = 0.f;
        #pragma unroll
        for (int c = 0; c < 16; ++c)
            acc = fmaf(svb[c], swp[c], acc);
        acc += __shfl_xor_sync(0xffffffffu, acc, 1);
        acc += __shfl_xor_sync(0xffffffffu, acc, 2);
        if (part == 0)
            out[b * CC + c2] = acc + bias;
    }
}

// ---------------------------------------------------------------------------
// Inputs (metadata order):
//   0: x        (32,12,128)   f32
//   1: W_heads  (8,128,64)    f32
//   2: a1_heads (8,64)        f32   (unused: softmax over identical rows is uniform)
//   3: a2_heads (8,64)        f32   (unused)
//   4: W_out    (512,64)      f32
//   5: a1_out   (64)          f32   (unused)
//   6: a2_out   (64)          f32   (unused)
//   7: Wf       (64,32768)    f32
//   8: bf       (64)          f32
// Output: (32,64) f32
// ---------------------------------------------------------------------------
extern "C" void kernel_launch(void* const* d_in, const int* in_sizes, int n_in,
                              void* d_out, int out_size)
{
    const float* x       = (const float*)d_in[0];
    const float* W_heads = (const float*)d_in[1];
    const float* W_out   = (const float*)d_in[4];
    const float* Wf      = (const float*)d_in[7];
    const float* bf      = (const float*)d_in[8];
    float* out = (float*)d_out;

    kA_fused<<<TOTAL_BLOCKS, 256>>>(Wf, x, W_heads, W_out);
    kB_final<<<CC, 128>>>(bf, out);
}